// round 15
// baseline (speedup 1.0000x reference)
#include <cuda_runtime.h>
#include <cstdint>

// DbrxRouter: x[T,H] fp32 @ W[E=16,H]^T -> logits; softmax -> top4 -> /sum(top4)
// Outputs concatenated float32: weights [T,4] then indices [T,4] (as float).
//
// Two-kernel H-split design:
//  K1: 1024 CTAs = 512 token-tiles x 2 H-halves. CTA = 128 thr / 4 warps /
//      16 tokens x (H/2). Dual cp.async rings (x and W half-rows), xor-swizzled
//      smem (col ^ row&15) -> conflict-free 4-way-broadcast LDS. Col-sliced
//      warps, 4x4 lane register tile, packed f32x2 FMAs. Partial logits to a
//      static glog[2][T][16] (disjoint writes, no atomics).
//  K2: per-token sum of the two halves + stable top-4 + p=1 renorm + store.
// Rationale: R8/R12/R14 all sat at a latency equilibrium with ~13.8 warps/SM
// (grid-limited). H-split doubles CTAs at UNCHANGED W L2 traffic -> ~24
// warps/SM. STAGES=4 + launch_bounds(128,6) to fit 6 CTAs/SM.

#define NE      16
#define TOKC    16            // tokens per CTA
#define STAGES  4
#define PRO     3             // prologue depth (copy-issue is post-barrier)
#define CH4     16            // float4 per row per chunk (256B)
#define STG_B   4096          // bytes per stage (16 rows x 256B)
#define HS      2             // H slices
#define TMAX    8192

__device__ float glog[HS * TMAX * NE];   // partial logits [slice][token][expert]

__device__ __forceinline__ void fma2(unsigned long long& d,
                                     unsigned long long a,
                                     unsigned long long b) {
    asm("fma.rn.f32x2 %0, %1, %2, %0;" : "+l"(d) : "l"(a), "l"(b));
}
__device__ __forceinline__ float lo_f(unsigned long long v) {
    return __uint_as_float((unsigned)(v & 0xffffffffull));
}
__device__ __forceinline__ float hi_f(unsigned long long v) {
    return __uint_as_float((unsigned)(v >> 32));
}
__device__ __forceinline__ void cp16(uint32_t dst, const void* src) {
    asm volatile("cp.async.cg.shared.global [%0], [%1], 16;"
                 :: "r"(dst), "l"(src) : "memory");
}

__global__ __launch_bounds__(128, 6)
void router_main(const float* __restrict__ x, const float* __restrict__ w,
                 int T, int H4)
{
    __shared__ __align__(16) ulonglong2 xs[STAGES][TOKC][CH4];  // 16KB
    __shared__ __align__(16) ulonglong2 ws[STAGES][NE][CH4];    // 16KB

    const int tid  = threadIdx.x;
    const int wid  = tid >> 5;
    const int lane = tid & 31;
    const int eg   = lane >> 3;          // expert group: experts 4*eg..4*eg+3
    const int tg   = (lane >> 1) & 3;    // token group:  tokens  4*tg..4*tg+3
    const int ch   = lane & 1;           // col half within warp's slice
    const int s    = blockIdx.x & 1;     // H-slice
    const int ct0  = (blockIdx.x >> 1) * TOKC;
    if (ct0 >= T) return;

    const int H4h  = H4 >> 1;            // float4 per half-row (768)
    const int hb   = s * H4h;            // slice base (float4 units)
    const int NCH  = H4h / CH4;          // 48 chunks

    const ulonglong2* __restrict__ x2 = reinterpret_cast<const ulonglong2*>(x);
    const ulonglong2* __restrict__ w2 = reinterpret_cast<const ulonglong2*>(w);

    // ---- producer mapping: thread -> row crow, cols coff and coff+8 ----
    const int crow = tid >> 3;           // 0..15 (token slot / W row)
    const int coff = tid & 7;            // 0..7
    const ulonglong2* srcx = x2 + (size_t)min(ct0 + crow, T - 1) * H4 + hb + coff;
    const ulonglong2* srcw = w2 + (size_t)crow * H4 + hb + coff;

    const uint32_t xbase = (uint32_t)__cvta_generic_to_shared(&xs[0][0][0]);
    const uint32_t wbase = (uint32_t)__cvta_generic_to_shared(&ws[0][0][0]);
    // swizzled smem write offsets (16B units): col' = col ^ (row & 15)
    const int sw0 = (crow * CH4 + ((coff    ) ^ crow)) * 16;
    const int sw1 = (crow * CH4 + ((coff + 8) ^ crow)) * 16;

    // ---- consumer per-lane swizzled byte offsets ----
    int offx[4][2], offw[4][2];
    #pragma unroll
    for (int t = 0; t < 4; t++) {
        const int row = 4 * tg + t;
        #pragma unroll
        for (int jj = 0; jj < 2; jj++) {
            const int c4 = 4 * wid + 2 * jj + ch;
            offx[t][jj] = (row * CH4 + ((c4 ^ row) & 15)) * 16;
        }
    }
    #pragma unroll
    for (int e = 0; e < 4; e++) {
        const int row = 4 * eg + e;
        #pragma unroll
        for (int jj = 0; jj < 2; jj++) {
            const int c4 = 4 * wid + 2 * jj + ch;
            offw[e][jj] = (row * CH4 + ((c4 ^ row) & 15)) * 16;
        }
    }

    // Prologue: fill PRO stages.
    #pragma unroll
    for (int p = 0; p < PRO; ++p) {
        const uint32_t sb = (uint32_t)p * STG_B;
        cp16(xbase + sb + sw0, srcx + p * CH4);
        cp16(xbase + sb + sw1, srcx + p * CH4 + 8);
        cp16(wbase + sb + sw0, srcw + p * CH4);
        cp16(wbase + sb + sw1, srcw + p * CH4 + 8);
        asm volatile("cp.async.commit_group;" ::: "memory");
    }

    unsigned long long acc[4][4];        // [token-in-group][expert-in-group]
    #pragma unroll
    for (int t = 0; t < 4; t++)
        #pragma unroll
        for (int e = 0; e < 4; e++)
            acc[t][e] = 0ull;

    const char* xc0 = reinterpret_cast<const char*>(&xs[0][0][0]);
    const char* wc0 = reinterpret_cast<const char*>(&ws[0][0][0]);

    #pragma unroll 1
    for (int c = 0; c < NCH; ++c) {
        // Chunk c ready when <= PRO-1 groups in flight (groups are 1 chunk each).
        asm volatile("cp.async.wait_group %0;" :: "n"(PRO - 1) : "memory");
        __syncthreads();
        // Post-barrier issue into stage (c+PRO)%4 == (c-1)%4: all threads have
        // passed barrier c, so stage c-1 is fully consumed -> safe with 4 stages.
        const int cf = c + PRO;
        if (cf < NCH) {
            const uint32_t sb = (uint32_t)(cf % STAGES) * STG_B;
            cp16(xbase + sb + sw0, srcx + cf * CH4);
            cp16(xbase + sb + sw1, srcx + cf * CH4 + 8);
            cp16(wbase + sb + sw0, srcw + cf * CH4);
            cp16(wbase + sb + sw1, srcw + cf * CH4 + 8);
        }
        asm volatile("cp.async.commit_group;" ::: "memory");

        const char* xst = xc0 + (c % STAGES) * STG_B;
        const char* wst = wc0 + (c % STAGES) * STG_B;
        #pragma unroll
        for (int jj = 0; jj < 2; ++jj) {
            const ulonglong2 a0 = *(const ulonglong2*)(xst + offx[0][jj]);
            const ulonglong2 a1 = *(const ulonglong2*)(xst + offx[1][jj]);
            const ulonglong2 a2 = *(const ulonglong2*)(xst + offx[2][jj]);
            const ulonglong2 a3 = *(const ulonglong2*)(xst + offx[3][jj]);
            #pragma unroll
            for (int e = 0; e < 4; e++) {
                const ulonglong2 b = *(const ulonglong2*)(wst + offw[e][jj]);
                fma2(acc[0][e], a0.x, b.x); fma2(acc[0][e], a0.y, b.y);
                fma2(acc[1][e], a1.x, b.x); fma2(acc[1][e], a1.y, b.y);
                fma2(acc[2][e], a2.x, b.x); fma2(acc[2][e], a2.y, b.y);
                fma2(acc[3][e], a3.x, b.x); fma2(acc[3][e], a3.y, b.y);
            }
        }
    }

    // ---- epilogue: collapse packed halves, then col-partials ----
    float lgp[4][4];
    #pragma unroll
    for (int t = 0; t < 4; t++)
        #pragma unroll
        for (int e = 0; e < 4; e++)
            lgp[t][e] = lo_f(acc[t][e]) + hi_f(acc[t][e]);

    #pragma unroll
    for (int t = 0; t < 4; t++)
        #pragma unroll
        for (int e = 0; e < 4; e++)
            lgp[t][e] += __shfl_xor_sync(0xffffffffu, lgp[t][e], 1);

    __syncthreads();                     // ring dead -> reuse xs as scratch
    float* red = reinterpret_cast<float*>(&xs[0][0][0]); // [4][16 tok][16 exp]
    if (ch == 0) {
        #pragma unroll
        for (int t = 0; t < 4; t++)
            #pragma unroll
            for (int e = 0; e < 4; e++)
                red[(wid * TOKC + 4 * tg + t) * NE + (4 * eg + e)] = lgp[t][e];
    }
    __syncthreads();

    // threads 0..15: sum 4 warp-partials for one token, write slice partials.
    const int token = ct0 + tid;
    if (tid < TOKC && token < T) {
        float* gl = glog + ((size_t)s * T + token) * NE;
        #pragma unroll
        for (int e = 0; e < NE; e++)
            gl[e] = red[(0 * TOKC + tid) * NE + e]
                  + red[(1 * TOKC + tid) * NE + e]
                  + red[(2 * TOKC + tid) * NE + e]
                  + red[(3 * TOKC + tid) * NE + e];
    }
}

__global__ __launch_bounds__(256)
void router_top4(float* __restrict__ out, int T, int idx_off)
{
    const int token = blockIdx.x * blockDim.x + threadIdx.x;
    if (token >= T) return;

    const float* g0 = glog + (size_t)token * NE;
    const float* g1 = glog + ((size_t)T + token) * NE;
    float mylg[NE];
    #pragma unroll
    for (int e = 0; e < NE; e++)
        mylg[e] = g0[e] + g1[e];

    // Top-4, stable (strict '>' picks lowest index on ties, matching jax).
    unsigned mask = 0;
    float tw[4];
    int   ti[4];
    #pragma unroll
    for (int k = 0; k < 4; k++) {
        float best = -3.402823466e38f;
        int bi = 0;
        #pragma unroll
        for (int e = 0; e < NE; e++) {
            bool ok = (((mask >> e) & 1u) == 0u) && (mylg[e] > best);
            if (ok) { best = mylg[e]; bi = e; }
        }
        tw[k] = best; ti[k] = bi;
        mask |= (1u << bi);
    }
    // Softmax denominator cancels against p=1 renorm.
    const float m = tw[0];
    float s = 0.f;
    #pragma unroll
    for (int k = 0; k < 4; k++) { tw[k] = expf(tw[k] - m); s += tw[k]; }
    const float inv = 1.0f / s;
    #pragma unroll
    for (int k = 0; k < 4; k++) {
        out[token * 4 + k] = tw[k] * inv;
        if (idx_off >= 0) out[idx_off + token * 4 + k] = (float)ti[k];
    }
}

extern "C" void kernel_launch(void* const* d_in, const int* in_sizes, int n_in,
                              void* d_out, int out_size)
{
    const float* x = (const float*)d_in[0];
    const float* w = (const float*)d_in[1];

    const int H  = in_sizes[1] / NE;     // 6144
    const int T  = in_sizes[0] / H;      // 8192 (<= TMAX)
    const int H4 = H / 4;                // 1536 float4 per row

    const int idx_off = (out_size >= T * 8) ? (T * 4) : -1;

    const int tiles = (T + TOKC - 1) / TOKC;      // 512 token tiles
    router_main<<<tiles * HS, 128>>>(x, w, T, H4);
    router_top4<<<(T + 255) / 256, 256>>>((float*)d_out, T, idx_off);
}